// round 2
// baseline (speedup 1.0000x reference)
#include <cuda_runtime.h>

#define B_ 4096
#define T_ 24
#define I_ 128
#define H_ 512
#define WD_ 32
#define M_ (B_*T_)   // 98304

typedef unsigned long long ull;

// ---------------- scratch (device globals; no allocation) ----------------
__device__ float g_e    [M_*H_];   // e = sigmoid(xw @ w_e^T + b_e), [B*T, H]
__device__ float g_pre_o[M_*H_];   // [T, B, H]
__device__ float g_pre_r[M_*H_];
__device__ float g_pre_z[M_*H_];
__device__ float g_pre_h[M_*H_];
__device__ float g_h [B_*H_];
__device__ float g_ho[B_*H_];
__device__ float g_a [B_*H_];      // r * h_o
__device__ float g_z [B_*H_];
__device__ float g_Wrz [1024*640]; // [[w_rx|w_re];[w_zx|w_ze]]
__device__ float g_Wo  [512*384];  // [w_d|w_w|w_m]
__device__ float g_Wrzh[1024*512]; // [w_rh; w_zh]

__device__ __forceinline__ float sigf(float x){ return 1.f/(1.f + __expf(-x)); }

__device__ __forceinline__ void fma2(ull& d, ull a, ull b){
    asm("fma.rn.f32x2 %0, %1, %2, %0;" : "+l"(d) : "l"(a), "l"(b));
}
__device__ __forceinline__ ull pack2(float x){
    ull r; asm("mov.b64 %0, {%1, %1};" : "=l"(r) : "f"(x)); return r;
}

// ---------------- weight-concat + h0 init ----------------
__global__ void prep_k(const float* __restrict__ w_rx, const float* __restrict__ w_re,
                       const float* __restrict__ w_zx, const float* __restrict__ w_ze,
                       const float* __restrict__ w_d,  const float* __restrict__ w_w,
                       const float* __restrict__ w_m,
                       const float* __restrict__ w_rh, const float* __restrict__ w_zh)
{
    int i = blockIdx.x*blockDim.x + threadIdx.x;
    if (i < 1024*640){
        int r = i/640, c = i - r*640;
        float v;
        if (r < 512) v = (c < 128) ? w_rx[r*128+c] : w_re[r*512 + (c-128)];
        else { int rr = r-512; v = (c < 128) ? w_zx[rr*128+c] : w_ze[rr*512 + (c-128)]; }
        g_Wrz[i] = v;
    }
    if (i < 512*384){
        int r = i/384, c = i - r*384;
        int s = c >> 7, cc = c & 127;
        const float* p = (s==0) ? w_d : (s==1) ? w_w : w_m;
        g_Wo[i] = p[r*128+cc];
    }
    if (i < 1024*512){
        int r = i >> 9, c = i & 511;
        g_Wrzh[i] = (r < 512) ? w_rh[r*512+c] : w_zh[(r-512)*512+c];
    }
    if (i < B_*H_) g_h[i] = 0.f;
}

// ---------------- generic tiled GEMM: C = epilogue(A @ W^T) ----------------
// MODE 0: e      A=xw [M,32]      W=w_e                 -> g_e = sig(c + b_e)
// MODE 1: pre_rz A=[x|e] K=640    W=g_Wrz, N=1024       -> g_pre_r/g_pre_z (+bias), [T,B,H]
// MODE 2: pre_o  A=shifted x K=384 W=g_Wo               -> g_pre_o, [T,B,H]
// MODE 3: pre_h  A=x K=128        W=w_hx                -> g_pre_h (+b_h), [T,B,H]
// MODE 4: R1     A=g_h K=512      W=w_t                 -> g_ho = sig(pre_o_t + c)
// MODE 5: R2     A=g_ho K=512     W=g_Wrzh, N=1024      -> g_a = sig(pre_r_t+c)*g_ho ; g_z = sig(pre_z_t+c)
// MODE 6: R3     A=g_a K=512      W=w_hh                -> h = (1-z)*ho + z*tanh(pre_h_t+c); write h, out
template<int MODE>
__global__ void __launch_bounds__(256, 2)
gemm_k(const float* __restrict__ A, const float* __restrict__ W,
       const float* __restrict__ bias, const float* __restrict__ bias2,
       float* __restrict__ out, int K, int t)
{
    __shared__ float As[16][128];
    __shared__ float Bs[16][128];
    const int tid = threadIdx.x;
    const int tr = tid >> 4, tc = tid & 15;
    const int m0 = tr * 8, n0 = tc * 8;
    const int bm = blockIdx.y * 128, bn = blockIdx.x * 128;

    const float* Wp = (MODE==1) ? g_Wrz : (MODE==2) ? g_Wo : (MODE==5) ? g_Wrzh : W;

    ull acc[8][4];
#pragma unroll
    for (int i=0;i<8;i++)
#pragma unroll
        for (int j=0;j<4;j++) acc[i][j] = 0ull;

    for (int k0 = 0; k0 < K; k0 += 16){
#pragma unroll
        for (int it = 0; it < 2; it++){
            int id = tid + it*256;
            int r  = id >> 2, c4 = id & 3;
            int kk = k0 + c4*4;
            int gm = bm + r;
            float4 v;
            if (MODE==0)      v = *(const float4*)(A + gm*WD_ + kk);
            else if (MODE==1) v = (kk < I_) ? *(const float4*)(A + gm*I_ + kk)
                                            : *(const float4*)(g_e + gm*H_ + (kk - I_));
            else if (MODE==2){
                int s = kk >> 7;
                int shift = (s==0) ? 1 : (s==1) ? 7 : 30;
                int b = gm / T_;
                if (b < shift) v = make_float4(0.f,0.f,0.f,0.f);
                else           v = *(const float4*)(A + (gm - shift*T_)*I_ + (kk & 127));
            }
            else if (MODE==3) v = *(const float4*)(A + gm*I_ + kk);
            else if (MODE==4) v = *(const float4*)(g_h  + gm*H_ + kk);
            else if (MODE==5) v = *(const float4*)(g_ho + gm*H_ + kk);
            else              v = *(const float4*)(g_a  + gm*H_ + kk);
            As[c4*4+0][r]=v.x; As[c4*4+1][r]=v.y; As[c4*4+2][r]=v.z; As[c4*4+3][r]=v.w;

            int gn = bn + r;
            float4 w = *(const float4*)(Wp + gn*K + kk);
            Bs[c4*4+0][r]=w.x; Bs[c4*4+1][r]=w.y; Bs[c4*4+2][r]=w.z; Bs[c4*4+3][r]=w.w;
        }
        __syncthreads();
#pragma unroll
        for (int k = 0; k < 16; k++){
            float4 a0 = *(const float4*)&As[k][m0];
            float4 a1 = *(const float4*)&As[k][m0+4];
            float4 b0 = *(const float4*)&Bs[k][n0];
            float4 b1 = *(const float4*)&Bs[k][n0+4];
            ull bp[4];
            bp[0]=((ull*)&b0)[0]; bp[1]=((ull*)&b0)[1];
            bp[2]=((ull*)&b1)[0]; bp[3]=((ull*)&b1)[1];
            float av[8] = {a0.x,a0.y,a0.z,a0.w,a1.x,a1.y,a1.z,a1.w};
#pragma unroll
            for (int i=0;i<8;i++){
                ull ap = pack2(av[i]);
                fma2(acc[i][0], ap, bp[0]);
                fma2(acc[i][1], ap, bp[1]);
                fma2(acc[i][2], ap, bp[2]);
                fma2(acc[i][3], ap, bp[3]);
            }
        }
        __syncthreads();
    }

    // -------- epilogue --------
#pragma unroll
    for (int i=0;i<8;i++){
        int gm = bm + m0 + i;
        float cf[8];
#pragma unroll
        for (int j=0;j<4;j++){
            cf[2*j]   = __uint_as_float((unsigned)(acc[i][j] & 0xffffffffull));
            cf[2*j+1] = __uint_as_float((unsigned)(acc[i][j] >> 32));
        }
#pragma unroll
        for (int j=0;j<8;j++){
            int gn = bn + n0 + j;
            float c = cf[j];
            if (MODE==0){
                g_e[gm*H_+gn] = sigf(c + bias[gn]);
            } else if (MODE==1){
                int b = gm / T_, tt = gm - b*T_;
                int base = (tt*B_ + b)*H_;
                if (gn < H_) g_pre_r[base + gn]      = c + bias [gn];
                else         g_pre_z[base + gn - H_] = c + bias2[gn - H_];
            } else if (MODE==2){
                int b = gm / T_, tt = gm - b*T_;
                g_pre_o[(tt*B_+b)*H_ + gn] = c;
            } else if (MODE==3){
                int b = gm / T_, tt = gm - b*T_;
                g_pre_h[(tt*B_+b)*H_ + gn] = c + bias[gn];
            } else if (MODE==4){
                g_ho[gm*H_+gn] = sigf(g_pre_o[(t*B_+gm)*H_+gn] + c);
            } else if (MODE==5){
                if (gn < H_){
                    float r = sigf(g_pre_r[(t*B_+gm)*H_+gn] + c);
                    g_a[gm*H_+gn] = r * g_ho[gm*H_+gn];
                } else {
                    int n2 = gn - H_;
                    g_z[gm*H_+n2] = sigf(g_pre_z[(t*B_+gm)*H_+n2] + c);
                }
            } else { // MODE 6
                int idx = gm*H_+gn;
                float ht = tanhf(g_pre_h[(t*B_+gm)*H_+gn] + c);
                float z  = g_z[idx], ho = g_ho[idx];
                float hn = (1.f - z)*ho + z*ht;
                g_h[idx] = hn;
                out[(gm*T_ + t)*H_ + gn] = hn;
            }
        }
    }
}

// ---------------- launcher ----------------
extern "C" void kernel_launch(void* const* d_in, const int* in_sizes, int n_in,
                              void* d_out, int out_size)
{
    const float* x    = (const float*)d_in[0];
    const float* xw   = (const float*)d_in[1];
    const float* w_rx = (const float*)d_in[2];
    const float* w_rh = (const float*)d_in[3];
    const float* w_re = (const float*)d_in[4];
    const float* b_r  = (const float*)d_in[5];
    const float* w_zx = (const float*)d_in[6];
    const float* w_zh = (const float*)d_in[7];
    const float* w_ze = (const float*)d_in[8];
    const float* b_z  = (const float*)d_in[9];
    const float* w_hx = (const float*)d_in[10];
    const float* w_hh = (const float*)d_in[11];
    const float* b_h  = (const float*)d_in[12];
    const float* w_d  = (const float*)d_in[13];
    const float* w_w  = (const float*)d_in[14];
    const float* w_m  = (const float*)d_in[15];
    const float* w_t  = (const float*)d_in[16];
    const float* w_e  = (const float*)d_in[17];
    const float* b_e  = (const float*)d_in[18];
    float* out = (float*)d_out;

    prep_k<<<(B_*H_+255)/256, 256>>>(w_rx,w_re,w_zx,w_ze,w_d,w_w,w_m,w_rh,w_zh);

    // precompute (M = 98304 rows)
    gemm_k<0><<<dim3(4,768), 256>>>(xw, w_e, b_e, nullptr, nullptr,  32, 0);
    gemm_k<1><<<dim3(8,768), 256>>>(x, nullptr, b_r, b_z, nullptr, 640, 0);
    gemm_k<2><<<dim3(4,768), 256>>>(x, nullptr, nullptr, nullptr, nullptr, 384, 0);
    gemm_k<3><<<dim3(4,768), 256>>>(x, w_hx, b_h, nullptr, nullptr, 128, 0);

    // recurrence (M = 4096 rows per step)
    for (int t = 0; t < T_; t++){
        gemm_k<4><<<dim3(4,32), 256>>>(nullptr, w_t,  nullptr, nullptr, nullptr, 512, t);
        gemm_k<5><<<dim3(8,32), 256>>>(nullptr, nullptr, nullptr, nullptr, nullptr, 512, t);
        gemm_k<6><<<dim3(4,32), 256>>>(nullptr, w_hh, nullptr, nullptr, out, 512, t);
    }
}